// round 1
// baseline (speedup 1.0000x reference)
#include <cuda_runtime.h>
#include <math.h>

#define BB 8
#define SS 2048
#define HH 768
#define MTOT (BB*SS)   // 16384

// Scratch (device globals — no allocation allowed in kernel_launch)
__device__ float g_q[MTOT*HH];
__device__ float g_k[MTOT*HH];
__device__ float g_v[MTOT*HH];
__device__ float g_ctx[MTOT*HH];
__device__ float g_h[MTOT*HH];
__device__ float g_scores[(size_t)BB*SS*SS];

#define BM 64
#define BN 64
#define BK 16

// C = alpha*(A op(B)) [+ bias] [+ res], all row-major, all dims divisible by tiles.
// TRANSB=false: B is [K,N]. TRANSB=true: B is [N,K] (C[i][j] = sum_k A[i][k]*B[j][k]).
template<bool TRANSB>
__global__ __launch_bounds__(256)
void sgemm_kernel(const float* __restrict__ A, const float* __restrict__ B,
                  const float* __restrict__ bias, const float* __restrict__ res,
                  float* __restrict__ C, int M, int N, int K,
                  long long sA, long long sB, long long sC, float alpha)
{
    A += (long long)blockIdx.z * sA;
    B += (long long)blockIdx.z * sB;
    C += (long long)blockIdx.z * sC;

    __shared__ float As[BK][BM + 4];
    __shared__ float Bs[BK][BN + 4];

    const int tid = threadIdx.x;
    const int tx = tid & 15;         // 0..15 -> cols (x4)
    const int ty = tid >> 4;         // 0..15 -> rows (x4)
    const int m0 = blockIdx.y * BM;
    const int n0 = blockIdx.x * BN;

    // A-tile load map: 64 rows x 16 k, one float4 per thread
    const int am = tid >> 2;          // 0..63
    const int ak = (tid & 3) * 4;     // 0,4,8,12

    float acc[4][4] = {};

    for (int k0 = 0; k0 < K; k0 += BK) {
        // load A tile (transposed into smem: As[k][m])
        float4 av = *(const float4*)(A + (long long)(m0 + am) * K + k0 + ak);
        As[ak + 0][am] = av.x;
        As[ak + 1][am] = av.y;
        As[ak + 2][am] = av.z;
        As[ak + 3][am] = av.w;

        if (!TRANSB) {
            // B[K,N]: 16 rows x 64 cols, one float4 per thread
            const int bk = tid >> 4;          // 0..15
            const int bn = (tid & 15) * 4;    // 0..60
            float4 bv = *(const float4*)(B + (long long)(k0 + bk) * N + n0 + bn);
            *(float4*)&Bs[bk][bn] = bv;
        } else {
            // B[N,K]: 64 rows x 16 k, one float4 per thread, transpose into Bs[k][n]
            const int bn = tid >> 2;          // 0..63
            const int bk4 = (tid & 3) * 4;    // 0,4,8,12
            float4 bv = *(const float4*)(B + (long long)(n0 + bn) * K + k0 + bk4);
            Bs[bk4 + 0][bn] = bv.x;
            Bs[bk4 + 1][bn] = bv.y;
            Bs[bk4 + 2][bn] = bv.z;
            Bs[bk4 + 3][bn] = bv.w;
        }
        __syncthreads();

        #pragma unroll
        for (int k = 0; k < BK; k++) {
            float4 a = *(const float4*)&As[k][ty * 4];
            float4 b = *(const float4*)&Bs[k][tx * 4];
            float ar[4] = {a.x, a.y, a.z, a.w};
            float br[4] = {b.x, b.y, b.z, b.w};
            #pragma unroll
            for (int i = 0; i < 4; i++)
                #pragma unroll
                for (int j = 0; j < 4; j++)
                    acc[i][j] += ar[i] * br[j];
        }
        __syncthreads();
    }

    const int row = m0 + ty * 4;
    const int col = n0 + tx * 4;
    #pragma unroll
    for (int i = 0; i < 4; i++) {
        float4 o;
        o.x = acc[i][0] * alpha;
        o.y = acc[i][1] * alpha;
        o.z = acc[i][2] * alpha;
        o.w = acc[i][3] * alpha;
        if (bias) {
            o.x += bias[col + 0];
            o.y += bias[col + 1];
            o.z += bias[col + 2];
            o.w += bias[col + 3];
        }
        if (res) {
            const float* rr = res + (long long)(row + i) * N + col;
            o.x += rr[0]; o.y += rr[1]; o.z += rr[2]; o.w += rr[3];
        }
        *(float4*)(C + (long long)(row + i) * N + col) = o;
    }
}

// DeBERTa XSoftmax over rows of [B,S,S] with column mask [B,1,S].
// One block (256 thr) per row; 2048 cols -> 8 per thread.
__global__ __launch_bounds__(256)
void xsoftmax_kernel(float* __restrict__ scores, const int* __restrict__ mask)
{
    const int b = blockIdx.y;
    const int s = blockIdx.x;
    float* row = scores + ((size_t)b * SS + s) * SS;
    const int* mrow = mask + (size_t)b * SS;
    const int tid = threadIdx.x;

    const float NEG = -3.402823466e38f;
    float x[8];
    float mx = NEG;
    #pragma unroll
    for (int r = 0; r < 8; r++) {
        int t = tid + r * 256;
        float v = row[t];
        x[r] = mrow[t] ? v : NEG;
        mx = fmaxf(mx, x[r]);
    }

    __shared__ float red[256];
    red[tid] = mx;
    __syncthreads();
    for (int off = 128; off > 0; off >>= 1) {
        if (tid < off) red[tid] = fmaxf(red[tid], red[tid + off]);
        __syncthreads();
    }
    mx = red[0];
    __syncthreads();

    float sum = 0.f;
    #pragma unroll
    for (int r = 0; r < 8; r++) {
        float e = __expf(x[r] - mx);
        x[r] = e;
        sum += e;
    }
    red[tid] = sum;
    __syncthreads();
    for (int off = 128; off > 0; off >>= 1) {
        if (tid < off) red[tid] += red[tid + off];
        __syncthreads();
    }
    const float inv = 1.0f / red[0];

    #pragma unroll
    for (int r = 0; r < 8; r++) {
        int t = tid + r * 256;
        row[t] = mrow[t] ? x[r] * inv : 0.0f;
    }
}

// LayerNorm over H=768 per row. One block (256 thr) per row, 3 elems/thread.
__global__ __launch_bounds__(256)
void layernorm_kernel(const float* __restrict__ h,
                      const float* __restrict__ gamma,
                      const float* __restrict__ beta,
                      float* __restrict__ out)
{
    const int row = blockIdx.x;
    const float* r = h + (size_t)row * HH;
    float* o = out + (size_t)row * HH;
    const int tid = threadIdx.x;

    float v0 = r[tid], v1 = r[tid + 256], v2 = r[tid + 512];
    float s = v0 + v1 + v2;
    float ss = v0 * v0 + v1 * v1 + v2 * v2;

    __shared__ float rs[256], rss[256];
    rs[tid] = s; rss[tid] = ss;
    __syncthreads();
    for (int off = 128; off > 0; off >>= 1) {
        if (tid < off) { rs[tid] += rs[tid + off]; rss[tid] += rss[tid + off]; }
        __syncthreads();
    }
    const float mu = rs[0] * (1.0f / HH);
    const float var = rss[0] * (1.0f / HH) - mu * mu;
    const float rstd = rsqrtf(var + 1e-12f);

    o[tid]       = (v0 - mu) * rstd * gamma[tid]       + beta[tid];
    o[tid + 256] = (v1 - mu) * rstd * gamma[tid + 256] + beta[tid + 256];
    o[tid + 512] = (v2 - mu) * rstd * gamma[tid + 512] + beta[tid + 512];
}

extern "C" void kernel_launch(void* const* d_in, const int* in_sizes, int n_in,
                              void* d_out, int out_size)
{
    const float* X     = (const float*)d_in[0];
    const int*   mask  = (const int*)  d_in[1];
    const float* Wq    = (const float*)d_in[2];
    const float* bq    = (const float*)d_in[3];
    const float* Wk    = (const float*)d_in[4];
    const float* bk    = (const float*)d_in[5];
    const float* Wv    = (const float*)d_in[6];
    const float* bv    = (const float*)d_in[7];
    const float* Wo    = (const float*)d_in[8];
    const float* bo    = (const float*)d_in[9];
    const float* gamma = (const float*)d_in[10];
    const float* beta  = (const float*)d_in[11];
    float* out = (float*)d_out;

    float *q, *k, *v, *ctx, *h, *sc;
    cudaGetSymbolAddress((void**)&q,   g_q);
    cudaGetSymbolAddress((void**)&k,   g_k);
    cudaGetSymbolAddress((void**)&v,   g_v);
    cudaGetSymbolAddress((void**)&ctx, g_ctx);
    cudaGetSymbolAddress((void**)&h,   g_h);
    cudaGetSymbolAddress((void**)&sc,  g_scores);

    const dim3 blk(256);

    // 1) QKV projections: [16384,768] @ [768,768] + bias
    {
        dim3 grid(HH / BN, MTOT / BM, 1);
        sgemm_kernel<false><<<grid, blk>>>(X, Wq, bq, nullptr, q, MTOT, HH, HH, 0, 0, 0, 1.0f);
        sgemm_kernel<false><<<grid, blk>>>(X, Wk, bk, nullptr, k, MTOT, HH, HH, 0, 0, 0, 1.0f);
        sgemm_kernel<false><<<grid, blk>>>(X, Wv, bv, nullptr, v, MTOT, HH, HH, 0, 0, 0, 1.0f);
    }

    // 2) scores[b] = q[b] @ k[b]^T * 1/sqrt(H)   [2048,2048] per batch
    {
        dim3 grid(SS / BN, SS / BM, BB);
        const float scale = 1.0f / sqrtf((float)HH);
        sgemm_kernel<true><<<grid, blk>>>(q, k, nullptr, nullptr, sc,
                                          SS, SS, HH,
                                          (long long)SS * HH, (long long)SS * HH,
                                          (long long)SS * SS, scale);
    }

    // 3) masked softmax in-place
    {
        dim3 grid(SS, BB, 1);
        xsoftmax_kernel<<<grid, blk>>>(sc, mask);
    }

    // 4) ctx[b] = probs[b] @ v[b]   [2048,768] per batch
    {
        dim3 grid(HH / BN, SS / BM, BB);
        sgemm_kernel<false><<<grid, blk>>>(sc, v, nullptr, nullptr, ctx,
                                           SS, HH, SS,
                                           (long long)SS * SS, (long long)SS * HH,
                                           (long long)SS * HH, 1.0f);
    }

    // 5) h = ctx @ Wo + bo + X (residual fused in epilogue)
    {
        dim3 grid(HH / BN, MTOT / BM, 1);
        sgemm_kernel<false><<<grid, blk>>>(ctx, Wo, bo, X, h, MTOT, HH, HH, 0, 0, 0, 1.0f);
    }

    // 6) LayerNorm -> out
    {
        dim3 grid(MTOT, 1, 1);
        layernorm_kernel<<<grid, blk>>>(h, gamma, beta, out);
    }
}

// round 2
// speedup vs baseline: 3.0232x; 3.0232x over previous
#include <cuda_runtime.h>
#include <math.h>

#define BB 8
#define SS 2048
#define HH 768
#define MTOT (BB*SS)   // 16384

// Scratch (device globals — no allocation allowed)
__device__ float g_q[MTOT*HH];
__device__ float g_k[MTOT*HH];
__device__ float g_v[MTOT*HH];
__device__ float g_ctx[MTOT*HH];
__device__ float g_h[MTOT*HH];
__device__ float g_scores[(size_t)BB*SS*SS];

// ---------------- tf32 tensor-core GEMM ----------------
#define BM 128
#define BN 128
#define BK 16
#define ASTR 20     // [BM][BK+4] padded row stride (floats) — conflict-free frag LDS
#define BSTR 136    // [BK][BN+8] padded row stride for NN B     — conflict-free frag LDS

__device__ __forceinline__ unsigned f2tf(float x) {
    unsigned r; asm("cvt.rna.tf32.f32 %0, %1;" : "=r"(r) : "f"(x)); return r;
}
__device__ __forceinline__ void mma_tf32(float c[4],
        unsigned a0, unsigned a1, unsigned a2, unsigned a3,
        unsigned b0, unsigned b1) {
    asm volatile(
        "mma.sync.aligned.m16n8k8.row.col.f32.tf32.tf32.f32 "
        "{%0,%1,%2,%3}, {%4,%5,%6,%7}, {%8,%9}, {%0,%1,%2,%3};"
        : "+f"(c[0]), "+f"(c[1]), "+f"(c[2]), "+f"(c[3])
        : "r"(a0), "r"(a1), "r"(a2), "r"(a3), "r"(b0), "r"(b1));
}
__device__ __forceinline__ void cp16(float* smem, const float* gmem) {
    unsigned s = (unsigned)__cvta_generic_to_shared(smem);
    asm volatile("cp.async.ca.shared.global [%0], [%1], 16;" :: "r"(s), "l"(gmem));
}

// C = alpha*(A op(B)) [+bias] [+res]; row-major; dims divisible by tiles.
// TRANSB=false: B[K,N].  TRANSB=true: B[N,K] (C = A B^T).
template<bool TRANSB>
__global__ __launch_bounds__(256, 2)
void gemm_tf32(const float* __restrict__ A, const float* __restrict__ B,
               const float* __restrict__ bias, const float* __restrict__ res,
               float* __restrict__ C, int M, int N, int K,
               long long sA, long long sB, long long sC, float alpha)
{
    __shared__ float As[2][BM * ASTR];
    __shared__ float Bs[2][BM * ASTR];   // NT uses BM*ASTR=2560; NN uses BK*BSTR=2176

    A += (long long)blockIdx.z * sA;
    B += (long long)blockIdx.z * sB;
    C += (long long)blockIdx.z * sC;

    const int tid  = threadIdx.x;
    const int lane = tid & 31;
    const int warp = tid >> 5;
    const int g    = lane >> 2;     // groupID 0..7
    const int tg   = lane & 3;      // threadID_in_group 0..3
    const int wm   = warp & 3;      // 4 warps along M (32 rows each)
    const int wn   = warp >> 2;     // 2 warps along N (64 cols each)
    const int m0   = blockIdx.y * BM;
    const int n0   = blockIdx.x * BN;

    float acc[2][8][4] = {};

    auto loadA = [&](int buf, int k0) {
        #pragma unroll
        for (int i = 0; i < 2; i++) {
            int idx = tid + i * 256;
            int r = idx >> 2, c = (idx & 3) * 4;
            cp16(&As[buf][r * ASTR + c], A + (long long)(m0 + r) * K + k0 + c);
        }
    };
    auto loadB = [&](int buf, int k0) {
        #pragma unroll
        for (int i = 0; i < 2; i++) {
            int idx = tid + i * 256;
            if (TRANSB) {
                int r = idx >> 2, c = (idx & 3) * 4;       // r = n row, c = k
                cp16(&Bs[buf][r * ASTR + c], B + (long long)(n0 + r) * K + k0 + c);
            } else {
                int k = idx >> 5, c = (idx & 31) * 4;      // k row, c = n
                cp16(&Bs[buf][k * BSTR + c], B + (long long)(k0 + k) * N + n0 + c);
            }
        }
    };

    loadA(0, 0); loadB(0, 0);
    asm volatile("cp.async.commit_group;");

    const int KT = K / BK;
    for (int kt = 0; kt < KT; kt++) {
        asm volatile("cp.async.wait_group 0;");
        __syncthreads();
        const int cb = kt & 1;
        if (kt + 1 < KT) {
            loadA((kt + 1) & 1, (kt + 1) * BK);
            loadB((kt + 1) & 1, (kt + 1) * BK);
            asm volatile("cp.async.commit_group;");
        }

        #pragma unroll
        for (int ks = 0; ks < 2; ks++) {
            unsigned af[2][4];
            #pragma unroll
            for (int mt = 0; mt < 2; mt++) {
                int r = wm * 32 + mt * 16 + g;
                int c = ks * 8 + tg;
                af[mt][0] = f2tf(As[cb][ r      * ASTR + c    ]);
                af[mt][1] = f2tf(As[cb][(r + 8) * ASTR + c    ]);
                af[mt][2] = f2tf(As[cb][ r      * ASTR + c + 4]);
                af[mt][3] = f2tf(As[cb][(r + 8) * ASTR + c + 4]);
            }
            #pragma unroll
            for (int nt = 0; nt < 8; nt++) {
                int n = wn * 64 + nt * 8 + g;
                int k = ks * 8 + tg;
                unsigned b0, b1;
                if (TRANSB) {
                    b0 = f2tf(Bs[cb][n * ASTR + k    ]);
                    b1 = f2tf(Bs[cb][n * ASTR + k + 4]);
                } else {
                    b0 = f2tf(Bs[cb][ k      * BSTR + n]);
                    b1 = f2tf(Bs[cb][(k + 4) * BSTR + n]);
                }
                mma_tf32(acc[0][nt], af[0][0], af[0][1], af[0][2], af[0][3], b0, b1);
                mma_tf32(acc[1][nt], af[1][0], af[1][1], af[1][2], af[1][3], b0, b1);
            }
        }
    }

    // epilogue
    #pragma unroll
    for (int mt = 0; mt < 2; mt++) {
        #pragma unroll
        for (int nt = 0; nt < 8; nt++) {
            int row = m0 + wm * 32 + mt * 16 + g;
            int col = n0 + wn * 64 + nt * 8 + tg * 2;
            float2 v0 = make_float2(acc[mt][nt][0] * alpha, acc[mt][nt][1] * alpha);
            float2 v1 = make_float2(acc[mt][nt][2] * alpha, acc[mt][nt][3] * alpha);
            if (bias) {
                float2 bb = *(const float2*)(bias + col);
                v0.x += bb.x; v0.y += bb.y; v1.x += bb.x; v1.y += bb.y;
            }
            if (res) {
                float2 r0 = *(const float2*)(res + (long long)row * N + col);
                float2 r1 = *(const float2*)(res + (long long)(row + 8) * N + col);
                v0.x += r0.x; v0.y += r0.y; v1.x += r1.x; v1.y += r1.y;
            }
            *(float2*)(C + (long long)row * N + col) = v0;
            *(float2*)(C + (long long)(row + 8) * N + col) = v1;
        }
    }
}

// ---------------- XSoftmax ----------------
__global__ __launch_bounds__(256)
void xsoftmax_kernel(float* __restrict__ scores, const int* __restrict__ mask)
{
    const int b = blockIdx.y;
    const int s = blockIdx.x;
    float* row = scores + ((size_t)b * SS + s) * SS;
    const int* mrow = mask + (size_t)b * SS;
    const int tid = threadIdx.x;

    const float NEG = -3.402823466e38f;
    float x[8];
    float mx = NEG;
    #pragma unroll
    for (int r = 0; r < 8; r++) {
        int t = tid + r * 256;
        float v = row[t];
        x[r] = mrow[t] ? v : NEG;
        mx = fmaxf(mx, x[r]);
    }

    __shared__ float red[256];
    red[tid] = mx;
    __syncthreads();
    for (int off = 128; off > 0; off >>= 1) {
        if (tid < off) red[tid] = fmaxf(red[tid], red[tid + off]);
        __syncthreads();
    }
    mx = red[0];
    __syncthreads();

    float sum = 0.f;
    #pragma unroll
    for (int r = 0; r < 8; r++) {
        float e = __expf(x[r] - mx);
        x[r] = e;
        sum += e;
    }
    red[tid] = sum;
    __syncthreads();
    for (int off = 128; off > 0; off >>= 1) {
        if (tid < off) red[tid] += red[tid + off];
        __syncthreads();
    }
    const float inv = 1.0f / red[0];

    #pragma unroll
    for (int r = 0; r < 8; r++) {
        int t = tid + r * 256;
        row[t] = mrow[t] ? x[r] * inv : 0.0f;
    }
}

// ---------------- LayerNorm ----------------
__global__ __launch_bounds__(256)
void layernorm_kernel(const float* __restrict__ h,
                      const float* __restrict__ gamma,
                      const float* __restrict__ beta,
                      float* __restrict__ out)
{
    const int row = blockIdx.x;
    const float* r = h + (size_t)row * HH;
    float* o = out + (size_t)row * HH;
    const int tid = threadIdx.x;

    float v0 = r[tid], v1 = r[tid + 256], v2 = r[tid + 512];
    float s = v0 + v1 + v2;
    float ss = v0 * v0 + v1 * v1 + v2 * v2;

    __shared__ float rs[256], rss[256];
    rs[tid] = s; rss[tid] = ss;
    __syncthreads();
    for (int off = 128; off > 0; off >>= 1) {
        if (tid < off) { rs[tid] += rs[tid + off]; rss[tid] += rss[tid + off]; }
        __syncthreads();
    }
    const float mu = rs[0] * (1.0f / HH);
    const float var = rss[0] * (1.0f / HH) - mu * mu;
    const float rstd = rsqrtf(var + 1e-12f);

    o[tid]       = (v0 - mu) * rstd * gamma[tid]       + beta[tid];
    o[tid + 256] = (v1 - mu) * rstd * gamma[tid + 256] + beta[tid + 256];
    o[tid + 512] = (v2 - mu) * rstd * gamma[tid + 512] + beta[tid + 512];
}

extern "C" void kernel_launch(void* const* d_in, const int* in_sizes, int n_in,
                              void* d_out, int out_size)
{
    const float* X     = (const float*)d_in[0];
    const int*   mask  = (const int*)  d_in[1];
    const float* Wq    = (const float*)d_in[2];
    const float* bq    = (const float*)d_in[3];
    const float* Wk    = (const float*)d_in[4];
    const float* bk    = (const float*)d_in[5];
    const float* Wv    = (const float*)d_in[6];
    const float* bv    = (const float*)d_in[7];
    const float* Wo    = (const float*)d_in[8];
    const float* bo    = (const float*)d_in[9];
    const float* gamma = (const float*)d_in[10];
    const float* beta  = (const float*)d_in[11];
    float* out = (float*)d_out;

    float *q, *k, *v, *ctx, *h, *sc;
    cudaGetSymbolAddress((void**)&q,   g_q);
    cudaGetSymbolAddress((void**)&k,   g_k);
    cudaGetSymbolAddress((void**)&v,   g_v);
    cudaGetSymbolAddress((void**)&ctx, g_ctx);
    cudaGetSymbolAddress((void**)&h,   g_h);
    cudaGetSymbolAddress((void**)&sc,  g_scores);

    const dim3 blk(256);

    // 1) QKV projections: [16384,768] = X @ W + b
    {
        dim3 grid(HH / BN, MTOT / BM, 1);
        gemm_tf32<false><<<grid, blk>>>(X, Wq, bq, nullptr, q, MTOT, HH, HH, 0, 0, 0, 1.0f);
        gemm_tf32<false><<<grid, blk>>>(X, Wk, bk, nullptr, k, MTOT, HH, HH, 0, 0, 0, 1.0f);
        gemm_tf32<false><<<grid, blk>>>(X, Wv, bv, nullptr, v, MTOT, HH, HH, 0, 0, 0, 1.0f);
    }

    // 2) scores[b] = q[b] @ k[b]^T * 1/sqrt(H)
    {
        dim3 grid(SS / BN, SS / BM, BB);
        const float scale = 1.0f / sqrtf((float)HH);
        gemm_tf32<true><<<grid, blk>>>(q, k, nullptr, nullptr, sc,
                                       SS, SS, HH,
                                       (long long)SS * HH, (long long)SS * HH,
                                       (long long)SS * SS, scale);
    }

    // 3) masked softmax in-place
    {
        dim3 grid(SS, BB, 1);
        xsoftmax_kernel<<<grid, blk>>>(sc, mask);
    }

    // 4) ctx[b] = probs[b] @ v[b]
    {
        dim3 grid(HH / BN, SS / BM, BB);
        gemm_tf32<false><<<grid, blk>>>(sc, v, nullptr, nullptr, ctx,
                                        SS, HH, SS,
                                        (long long)SS * SS, (long long)SS * HH,
                                        (long long)SS * HH, 1.0f);
    }

    // 5) h = ctx @ Wo + bo + X
    {
        dim3 grid(HH / BN, MTOT / BM, 1);
        gemm_tf32<false><<<grid, blk>>>(ctx, Wo, bo, X, h, MTOT, HH, HH, 0, 0, 0, 1.0f);
    }

    // 6) LayerNorm -> out
    {
        dim3 grid(MTOT, 1, 1);
        layernorm_kernel<<<grid, blk>>>(h, gamma, beta, out);
    }
}

// round 3
// speedup vs baseline: 3.1463x; 1.0407x over previous
#include <cuda_runtime.h>
#include <math.h>

#define BB 8
#define SS 2048
#define HH 768
#define MTOT (BB*SS)   // 16384

// Scratch (device globals — no allocation allowed)
__device__ float g_q[MTOT*HH];
__device__ float g_k[MTOT*HH];
__device__ float g_v[MTOT*HH];
__device__ float g_ctx[MTOT*HH];
__device__ float g_h[MTOT*HH];
__device__ float g_scores[(size_t)BB*SS*SS];
__device__ float g_xc[MTOT*HH];        // tf32-rounded X
__device__ float g_wc[4*HH*HH];        // tf32-rounded Wq,Wk,Wv,Wo

// ---------------- tf32 helpers ----------------
__device__ __forceinline__ float tf32r(float x) {
    unsigned r; asm("cvt.rna.tf32.f32 %0, %1;" : "=r"(r) : "f"(x));
    return __uint_as_float(r);
}

// elementwise round-to-tf32, float4 vectorized (n divisible by 4)
__global__ __launch_bounds__(256)
void tf32_round_kernel(const float* __restrict__ in, float* __restrict__ out, int n4)
{
    int i = blockIdx.x * 256 + threadIdx.x;
    if (i >= n4) return;
    float4 v = ((const float4*)in)[i];
    v.x = tf32r(v.x); v.y = tf32r(v.y); v.z = tf32r(v.z); v.w = tf32r(v.w);
    ((float4*)out)[i] = v;
}

// ---------------- tf32 tensor-core GEMM ----------------
#define BM 128
#define BN 128
#define BK 16
#define ASTR 20     // [BM][BK+4] padded row stride — conflict-free frag LDS
#define BSTR 136    // [BK][BN+8] padded row stride for NN B

__device__ __forceinline__ void mma_tf32(float c[4],
        unsigned a0, unsigned a1, unsigned a2, unsigned a3,
        unsigned b0, unsigned b1) {
    asm volatile(
        "mma.sync.aligned.m16n8k8.row.col.f32.tf32.tf32.f32 "
        "{%0,%1,%2,%3}, {%4,%5,%6,%7}, {%8,%9}, {%0,%1,%2,%3};"
        : "+f"(c[0]), "+f"(c[1]), "+f"(c[2]), "+f"(c[3])
        : "r"(a0), "r"(a1), "r"(a2), "r"(a3), "r"(b0), "r"(b1));
}
__device__ __forceinline__ void cp16(float* smem, const float* gmem) {
    unsigned s = (unsigned)__cvta_generic_to_shared(smem);
    asm volatile("cp.async.ca.shared.global [%0], [%1], 16;" :: "r"(s), "l"(gmem));
}

// C = alpha*(A op(B)) [+bias] [+res]; row-major; dims divisible by tiles.
// A and B MUST already be tf32-rounded. roundOut: round C to tf32 on store.
// TRANSB=false: B[K,N].  TRANSB=true: B[N,K] (C = A B^T).
template<bool TRANSB>
__global__ __launch_bounds__(256, 2)
void gemm_tf32(const float* __restrict__ A, const float* __restrict__ B,
               const float* __restrict__ bias, const float* __restrict__ res,
               float* __restrict__ C, int M, int N, int K,
               long long sA, long long sB, long long sC, float alpha, int roundOut)
{
    __shared__ float As[2][BM * ASTR];
    __shared__ float Bs[2][BM * ASTR];   // NT: BM*ASTR=2560; NN: BK*BSTR=2176

    A += (long long)blockIdx.z * sA;
    B += (long long)blockIdx.z * sB;
    C += (long long)blockIdx.z * sC;

    const int tid  = threadIdx.x;
    const int lane = tid & 31;
    const int warp = tid >> 5;
    const int g    = lane >> 2;     // 0..7
    const int tg   = lane & 3;      // 0..3
    const int wm   = warp & 3;      // 4 warps on M
    const int wn   = warp >> 2;     // 2 warps on N
    const int m0   = blockIdx.y * BM;
    const int n0   = blockIdx.x * BN;

    float acc[2][8][4] = {};

    auto loadA = [&](int buf, int k0) {
        #pragma unroll
        for (int i = 0; i < 2; i++) {
            int idx = tid + i * 256;
            int r = idx >> 2, c = (idx & 3) * 4;
            cp16(&As[buf][r * ASTR + c], A + (long long)(m0 + r) * K + k0 + c);
        }
    };
    auto loadB = [&](int buf, int k0) {
        #pragma unroll
        for (int i = 0; i < 2; i++) {
            int idx = tid + i * 256;
            if (TRANSB) {
                int r = idx >> 2, c = (idx & 3) * 4;
                cp16(&Bs[buf][r * ASTR + c], B + (long long)(n0 + r) * K + k0 + c);
            } else {
                int k = idx >> 5, c = (idx & 31) * 4;
                cp16(&Bs[buf][k * BSTR + c], B + (long long)(k0 + k) * N + n0 + c);
            }
        }
    };

    loadA(0, 0); loadB(0, 0);
    asm volatile("cp.async.commit_group;");

    const int KT = K / BK;
    for (int kt = 0; kt < KT; kt++) {
        asm volatile("cp.async.wait_group 0;");
        __syncthreads();
        const int cb = kt & 1;
        if (kt + 1 < KT) {
            loadA((kt + 1) & 1, (kt + 1) * BK);
            loadB((kt + 1) & 1, (kt + 1) * BK);
            asm volatile("cp.async.commit_group;");
        }

        #pragma unroll
        for (int ks = 0; ks < 2; ks++) {
            unsigned af[2][4];
            #pragma unroll
            for (int mt = 0; mt < 2; mt++) {
                int r = wm * 32 + mt * 16 + g;
                int c = ks * 8 + tg;
                af[mt][0] = __float_as_uint(As[cb][ r      * ASTR + c    ]);
                af[mt][1] = __float_as_uint(As[cb][(r + 8) * ASTR + c    ]);
                af[mt][2] = __float_as_uint(As[cb][ r      * ASTR + c + 4]);
                af[mt][3] = __float_as_uint(As[cb][(r + 8) * ASTR + c + 4]);
            }
            #pragma unroll
            for (int nt = 0; nt < 8; nt++) {
                int n = wn * 64 + nt * 8 + g;
                int k = ks * 8 + tg;
                unsigned b0, b1;
                if (TRANSB) {
                    b0 = __float_as_uint(Bs[cb][n * ASTR + k    ]);
                    b1 = __float_as_uint(Bs[cb][n * ASTR + k + 4]);
                } else {
                    b0 = __float_as_uint(Bs[cb][ k      * BSTR + n]);
                    b1 = __float_as_uint(Bs[cb][(k + 4) * BSTR + n]);
                }
                mma_tf32(acc[0][nt], af[0][0], af[0][1], af[0][2], af[0][3], b0, b1);
                mma_tf32(acc[1][nt], af[1][0], af[1][1], af[1][2], af[1][3], b0, b1);
            }
        }
    }

    // epilogue
    #pragma unroll
    for (int mt = 0; mt < 2; mt++) {
        #pragma unroll
        for (int nt = 0; nt < 8; nt++) {
            int row = m0 + wm * 32 + mt * 16 + g;
            int col = n0 + wn * 64 + nt * 8 + tg * 2;
            float2 v0 = make_float2(acc[mt][nt][0] * alpha, acc[mt][nt][1] * alpha);
            float2 v1 = make_float2(acc[mt][nt][2] * alpha, acc[mt][nt][3] * alpha);
            if (bias) {
                float2 bb = *(const float2*)(bias + col);
                v0.x += bb.x; v0.y += bb.y; v1.x += bb.x; v1.y += bb.y;
            }
            if (res) {
                float2 r0 = *(const float2*)(res + (long long)row * N + col);
                float2 r1 = *(const float2*)(res + (long long)(row + 8) * N + col);
                v0.x += r0.x; v0.y += r0.y; v1.x += r1.x; v1.y += r1.y;
            }
            if (roundOut) {
                v0.x = tf32r(v0.x); v0.y = tf32r(v0.y);
                v1.x = tf32r(v1.x); v1.y = tf32r(v1.y);
            }
            *(float2*)(C + (long long)row * N + col) = v0;
            *(float2*)(C + (long long)(row + 8) * N + col) = v1;
        }
    }
}

// ---------------- XSoftmax (writes tf32-rounded probs) ----------------
__global__ __launch_bounds__(256)
void xsoftmax_kernel(float* __restrict__ scores, const int* __restrict__ mask)
{
    const int b = blockIdx.y;
    const int s = blockIdx.x;
    float* row = scores + ((size_t)b * SS + s) * SS;
    const int* mrow = mask + (size_t)b * SS;
    const int tid = threadIdx.x;

    const float NEG = -3.402823466e38f;
    float x[8];
    float mx = NEG;
    #pragma unroll
    for (int r = 0; r < 8; r++) {
        int t = tid + r * 256;
        float v = row[t];
        x[r] = mrow[t] ? v : NEG;
        mx = fmaxf(mx, x[r]);
    }

    __shared__ float red[256];
    red[tid] = mx;
    __syncthreads();
    for (int off = 128; off > 0; off >>= 1) {
        if (tid < off) red[tid] = fmaxf(red[tid], red[tid + off]);
        __syncthreads();
    }
    mx = red[0];
    __syncthreads();

    float sum = 0.f;
    #pragma unroll
    for (int r = 0; r < 8; r++) {
        float e = __expf(x[r] - mx);
        x[r] = e;
        sum += e;
    }
    red[tid] = sum;
    __syncthreads();
    for (int off = 128; off > 0; off >>= 1) {
        if (tid < off) red[tid] += red[tid + off];
        __syncthreads();
    }
    const float inv = 1.0f / red[0];

    #pragma unroll
    for (int r = 0; r < 8; r++) {
        int t = tid + r * 256;
        row[t] = mrow[t] ? tf32r(x[r] * inv) : 0.0f;
    }
}

// ---------------- LayerNorm ----------------
__global__ __launch_bounds__(256)
void layernorm_kernel(const float* __restrict__ h,
                      const float* __restrict__ gamma,
                      const float* __restrict__ beta,
                      float* __restrict__ out)
{
    const int row = blockIdx.x;
    const float* r = h + (size_t)row * HH;
    float* o = out + (size_t)row * HH;
    const int tid = threadIdx.x;

    float v0 = r[tid], v1 = r[tid + 256], v2 = r[tid + 512];
    float s = v0 + v1 + v2;
    float ss = v0 * v0 + v1 * v1 + v2 * v2;

    __shared__ float rs[256], rss[256];
    rs[tid] = s; rss[tid] = ss;
    __syncthreads();
    for (int off = 128; off > 0; off >>= 1) {
        if (tid < off) { rs[tid] += rs[tid + off]; rss[tid] += rss[tid + off]; }
        __syncthreads();
    }
    const float mu = rs[0] * (1.0f / HH);
    const float var = rss[0] * (1.0f / HH) - mu * mu;
    const float rstd = rsqrtf(var + 1e-12f);

    o[tid]       = (v0 - mu) * rstd * gamma[tid]       + beta[tid];
    o[tid + 256] = (v1 - mu) * rstd * gamma[tid + 256] + beta[tid + 256];
    o[tid + 512] = (v2 - mu) * rstd * gamma[tid + 512] + beta[tid + 512];
}

extern "C" void kernel_launch(void* const* d_in, const int* in_sizes, int n_in,
                              void* d_out, int out_size)
{
    const float* X     = (const float*)d_in[0];
    const int*   mask  = (const int*)  d_in[1];
    const float* Wq    = (const float*)d_in[2];
    const float* bq    = (const float*)d_in[3];
    const float* Wk    = (const float*)d_in[4];
    const float* bk    = (const float*)d_in[5];
    const float* Wv    = (const float*)d_in[6];
    const float* bv    = (const float*)d_in[7];
    const float* Wo    = (const float*)d_in[8];
    const float* bo    = (const float*)d_in[9];
    const float* gamma = (const float*)d_in[10];
    const float* beta  = (const float*)d_in[11];
    float* out = (float*)d_out;

    float *q, *k, *v, *ctx, *h, *sc, *xc, *wc;
    cudaGetSymbolAddress((void**)&q,   g_q);
    cudaGetSymbolAddress((void**)&k,   g_k);
    cudaGetSymbolAddress((void**)&v,   g_v);
    cudaGetSymbolAddress((void**)&ctx, g_ctx);
    cudaGetSymbolAddress((void**)&h,   g_h);
    cudaGetSymbolAddress((void**)&sc,  g_scores);
    cudaGetSymbolAddress((void**)&xc,  g_xc);
    cudaGetSymbolAddress((void**)&wc,  g_wc);

    float* wqc = wc;
    float* wkc = wc + (size_t)HH * HH;
    float* wvc = wc + (size_t)2 * HH * HH;
    float* woc = wc + (size_t)3 * HH * HH;

    const dim3 blk(256);

    // 0) pre-round X and weights to tf32
    {
        int n4x = MTOT * HH / 4;
        tf32_round_kernel<<<(n4x + 255) / 256, blk>>>(X, xc, n4x);
        int n4w = HH * HH / 4;
        tf32_round_kernel<<<(n4w + 255) / 256, blk>>>(Wq, wqc, n4w);
        tf32_round_kernel<<<(n4w + 255) / 256, blk>>>(Wk, wkc, n4w);
        tf32_round_kernel<<<(n4w + 255) / 256, blk>>>(Wv, wvc, n4w);
        tf32_round_kernel<<<(n4w + 255) / 256, blk>>>(Wo, woc, n4w);
    }

    // 1) QKV projections (outputs rounded: q,k,v feed later MMAs)
    {
        dim3 grid(HH / BN, MTOT / BM, 1);
        gemm_tf32<false><<<grid, blk>>>(xc, wqc, bq, nullptr, q, MTOT, HH, HH, 0, 0, 0, 1.0f, 1);
        gemm_tf32<false><<<grid, blk>>>(xc, wkc, bk, nullptr, k, MTOT, HH, HH, 0, 0, 0, 1.0f, 1);
        gemm_tf32<false><<<grid, blk>>>(xc, wvc, bv, nullptr, v, MTOT, HH, HH, 0, 0, 0, 1.0f, 1);
    }

    // 2) scores[b] = q[b] @ k[b]^T * 1/sqrt(H)  (fp32 out; softmax rounds)
    {
        dim3 grid(SS / BN, SS / BM, BB);
        const float scale = 1.0f / sqrtf((float)HH);
        gemm_tf32<true><<<grid, blk>>>(q, k, nullptr, nullptr, sc,
                                       SS, SS, HH,
                                       (long long)SS * HH, (long long)SS * HH,
                                       (long long)SS * SS, scale, 0);
    }

    // 3) masked softmax in-place (writes tf32-rounded probs)
    {
        dim3 grid(SS, BB, 1);
        xsoftmax_kernel<<<grid, blk>>>(sc, mask);
    }

    // 4) ctx[b] = probs[b] @ v[b]  (rounded out: feeds final GEMM)
    {
        dim3 grid(HH / BN, SS / BM, BB);
        gemm_tf32<false><<<grid, blk>>>(sc, v, nullptr, nullptr, ctx,
                                        SS, HH, SS,
                                        (long long)SS * SS, (long long)SS * HH,
                                        (long long)SS * HH, 1.0f, 1);
    }

    // 5) h = ctx @ Wo + bo + X (fp32 out)
    {
        dim3 grid(HH / BN, MTOT / BM, 1);
        gemm_tf32<false><<<grid, blk>>>(ctx, woc, bo, X, h, MTOT, HH, HH, 0, 0, 0, 1.0f, 0);
    }

    // 6) LayerNorm -> out
    {
        dim3 grid(MTOT, 1, 1);
        layernorm_kernel<<<grid, blk>>>(h, gamma, beta, out);
    }
}

// round 5
// speedup vs baseline: 5.0738x; 1.6126x over previous
#include <cuda_runtime.h>
#include <cuda_fp16.h>
#include <math.h>
#include <stdint.h>

#define BB 8
#define SS 2048
#define HH 768
#define MTOT (BB*SS)   // 16384

// ---------------- scratch (device globals) ----------------
__device__ __half g_xh[MTOT*HH];
__device__ __half g_wt[4*HH*HH];                 // W^T fp16 (q,k,v,o), [N][K]
__device__ __half g_qh[MTOT*HH];
__device__ __half g_kh[MTOT*HH];
__device__ __half g_vh[MTOT*HH];
__device__ __half g_vt[MTOT*HH];                 // v^T per batch [H][S]
__device__ __half g_ph[(size_t)BB*SS*SS];
__device__ __half g_ch[MTOT*HH];
__device__ float  g_scores[(size_t)BB*SS*SS];
__device__ float  g_h[MTOT*HH];

// ---------------- fp16 tensor-core GEMM (NT only: C = alpha*A@B^T) ----------------
// A: [M,K] row-major fp16.  B: [N,K] row-major fp16 (K-major).
// BM=BN=128, BK=32. 256 threads: 4 warps on M (32 rows), 2 on N (64 cols).
#define BMH 128
#define BNH 128
#define BKH 32
#define ROWB 80                 // padded row stride in BYTES (32 halfs = 64B -> 80B)
#define TILEB (BMH*ROWB)        // 10240 bytes per operand tile
#define STAGEB (2*TILEB)        // A + B per stage

__device__ __forceinline__ void cp16(void* smem, const void* gmem){
    uint32_t s;
    asm("{ .reg .u64 t; cvta.to.shared.u64 t, %1; cvt.u32.u64 %0, t; }" : "=r"(s) : "l"(smem));
    asm volatile("cp.async.ca.shared.global [%0], [%1], 16;" :: "r"(s), "l"(gmem));
}
__device__ __forceinline__ void mma_f16(float c[4],
        uint32_t a0, uint32_t a1, uint32_t a2, uint32_t a3,
        uint32_t b0, uint32_t b1){
    asm volatile(
        "mma.sync.aligned.m16n8k16.row.col.f32.f16.f16.f32 "
        "{%0,%1,%2,%3}, {%4,%5,%6,%7}, {%8,%9}, {%0,%1,%2,%3};"
        : "+f"(c[0]), "+f"(c[1]), "+f"(c[2]), "+f"(c[3])
        : "r"(a0), "r"(a1), "r"(a2), "r"(a3), "r"(b0), "r"(b1));
}

__global__ __launch_bounds__(256, 2)
void gemm_f16(const __half* __restrict__ A, const __half* __restrict__ B,
              const float* __restrict__ bias, const float* __restrict__ res,
              float* __restrict__ Cf, __half* __restrict__ Ch,
              int K, int ldC, long long sA, long long sB, long long sC, float alpha)
{
    __shared__ __align__(128) char smbuf[2][STAGEB];

    A += (size_t)blockIdx.z * sA;
    B += (size_t)blockIdx.z * sB;
    if (Cf) Cf += (size_t)blockIdx.z * sC;
    if (Ch) Ch += (size_t)blockIdx.z * sC;

    const int tid  = threadIdx.x;
    const int lane = tid & 31;
    const int warp = tid >> 5;
    const int g    = lane >> 2;     // 0..7
    const int tg   = lane & 3;      // 0..3
    const int wm   = warp & 3;      // 4 warps on M (32 rows)
    const int wn   = warp >> 2;     // 2 warps on N (64 cols)
    const int m0   = blockIdx.y * BMH;
    const int n0   = blockIdx.x * BNH;
    const int NK   = K / BKH;

    float acc[2][8][4] = {};

    auto fill = [&](int buf, int kt){
        char* sA_ = smbuf[buf];
        char* sB_ = smbuf[buf] + TILEB;
        const int k0 = kt * BKH;
        #pragma unroll
        for (int i = 0; i < 2; i++){
            int idx = tid + i * 256;
            int r = idx >> 2, c = idx & 3;
            cp16(sA_ + r * ROWB + c * 16, A + (size_t)(m0 + r) * K + k0 + c * 8);
        }
        #pragma unroll
        for (int i = 0; i < 2; i++){
            int idx = tid + i * 256;
            int r = idx >> 2, c = idx & 3;
            cp16(sB_ + r * ROWB + c * 16, B + (size_t)(n0 + r) * K + k0 + c * 8);
        }
        asm volatile("cp.async.commit_group;");
    };

    fill(0, 0);

    for (int kt = 0; kt < NK; kt++){
        asm volatile("cp.async.wait_group 0;");
        __syncthreads();
        if (kt + 1 < NK) fill((kt + 1) & 1, kt + 1);

        const char* As = smbuf[kt & 1];
        const char* Bs = smbuf[kt & 1] + TILEB;

        #pragma unroll
        for (int ks = 0; ks < 2; ks++){
            uint32_t af[2][4];
            #pragma unroll
            for (int mt = 0; mt < 2; mt++){
                int r = wm * 32 + mt * 16 + g;
                int kb = (ks * 16 + 2 * tg) * 2;     // byte offset in row
                af[mt][0] = *(const uint32_t*)(As + (size_t) r      * ROWB + kb);
                af[mt][1] = *(const uint32_t*)(As + (size_t)(r + 8) * ROWB + kb);
                af[mt][2] = *(const uint32_t*)(As + (size_t) r      * ROWB + kb + 16);
                af[mt][3] = *(const uint32_t*)(As + (size_t)(r + 8) * ROWB + kb + 16);
            }
            #pragma unroll
            for (int nt = 0; nt < 8; nt++){
                int n = wn * 64 + nt * 8 + g;
                int kb = (ks * 16 + 2 * tg) * 2;
                uint32_t b0 = *(const uint32_t*)(Bs + (size_t)n * ROWB + kb);
                uint32_t b1 = *(const uint32_t*)(Bs + (size_t)n * ROWB + kb + 16);
                mma_f16(acc[0][nt], af[0][0], af[0][1], af[0][2], af[0][3], b0, b1);
                mma_f16(acc[1][nt], af[1][0], af[1][1], af[1][2], af[1][3], b0, b1);
            }
        }
        __syncthreads();
    }

    // epilogue: c0,c1 = (row g, cols 2tg,2tg+1), c2,c3 = row g+8
    #pragma unroll
    for (int mt = 0; mt < 2; mt++){
        #pragma unroll
        for (int nt = 0; nt < 8; nt++){
            int row = m0 + wm * 32 + mt * 16 + g;
            int col = n0 + wn * 64 + nt * 8 + tg * 2;
            float2 v0 = make_float2(acc[mt][nt][0] * alpha, acc[mt][nt][1] * alpha);
            float2 v1 = make_float2(acc[mt][nt][2] * alpha, acc[mt][nt][3] * alpha);
            if (bias){
                float2 bb = *(const float2*)(bias + col);
                v0.x += bb.x; v0.y += bb.y; v1.x += bb.x; v1.y += bb.y;
            }
            if (res){
                float2 r0 = *(const float2*)(res + (size_t)row * ldC + col);
                float2 r1 = *(const float2*)(res + (size_t)(row + 8) * ldC + col);
                v0.x += r0.x; v0.y += r0.y; v1.x += r1.x; v1.y += r1.y;
            }
            if (Cf){
                *(float2*)(Cf + (size_t)row * ldC + col) = v0;
                *(float2*)(Cf + (size_t)(row + 8) * ldC + col) = v1;
            }
            if (Ch){
                *(__half2*)(Ch + (size_t)row * ldC + col) = __floats2half2_rn(v0.x, v0.y);
                *(__half2*)(Ch + (size_t)(row + 8) * ldC + col) = __floats2half2_rn(v1.x, v1.y);
            }
        }
    }
}

// ---------------- conversions ----------------
__global__ __launch_bounds__(256)
void f32_to_f16(const float4* __restrict__ in, __half2* __restrict__ out, int n4)
{
    int i = blockIdx.x * 256 + threadIdx.x;
    if (i >= n4) return;
    float4 v = in[i];
    out[2*i]   = __floats2half2_rn(v.x, v.y);
    out[2*i+1] = __floats2half2_rn(v.z, v.w);
}

// fp32 [R][C] -> fp16 [C][R]
__global__ __launch_bounds__(256)
void transpose_f32_to_f16(const float* __restrict__ in, __half* __restrict__ outT,
                          int R, int C)
{
    __shared__ float t[32][33];
    const int c0 = blockIdx.x * 32, r0 = blockIdx.y * 32;
    const int tx = threadIdx.x & 31, ty = threadIdx.x >> 5;
    #pragma unroll
    for (int i = 0; i < 4; i++)
        t[ty + 8*i][tx] = in[(size_t)(r0 + ty + 8*i) * C + c0 + tx];
    __syncthreads();
    #pragma unroll
    for (int i = 0; i < 4; i++)
        outT[(size_t)(c0 + ty + 8*i) * R + r0 + tx] = __float2half(t[tx][ty + 8*i]);
}

// fp16 [R][C] -> fp16 [C][R], batched via z
__global__ __launch_bounds__(256)
void transpose_f16(const __half* __restrict__ in, __half* __restrict__ outT,
                   int R, int C, long long sIn, long long sOut)
{
    __shared__ float t[32][33];
    in   += (size_t)blockIdx.z * sIn;
    outT += (size_t)blockIdx.z * sOut;
    const int c0 = blockIdx.x * 32, r0 = blockIdx.y * 32;
    const int tx = threadIdx.x & 31, ty = threadIdx.x >> 5;
    #pragma unroll
    for (int i = 0; i < 4; i++)
        t[ty + 8*i][tx] = __half2float(in[(size_t)(r0 + ty + 8*i) * C + c0 + tx]);
    __syncthreads();
    #pragma unroll
    for (int i = 0; i < 4; i++)
        outT[(size_t)(c0 + ty + 8*i) * R + r0 + tx] = __float2half(t[tx][ty + 8*i]);
}

// ---------------- XSoftmax -> fp16 probs ----------------
__global__ __launch_bounds__(256)
void xsoftmax_f16(const float* __restrict__ scores, const int* __restrict__ mask,
                  __half* __restrict__ probs)
{
    const int b = blockIdx.y;
    const int s = blockIdx.x;
    const float* row = scores + ((size_t)b * SS + s) * SS;
    const int* mrow = mask + (size_t)b * SS;
    __half* pr = probs + ((size_t)b * SS + s) * SS;
    const int tid = threadIdx.x;

    const float NEG = -3.402823466e38f;
    float x[8];
    float mx = NEG;
    #pragma unroll
    for (int r = 0; r < 8; r++){
        int t = tid + r * 256;
        float v = row[t];
        x[r] = mrow[t] ? v : NEG;
        mx = fmaxf(mx, x[r]);
    }
    __shared__ float red[256];
    red[tid] = mx; __syncthreads();
    for (int off = 128; off > 0; off >>= 1){
        if (tid < off) red[tid] = fmaxf(red[tid], red[tid + off]);
        __syncthreads();
    }
    mx = red[0]; __syncthreads();

    float sum = 0.f;
    #pragma unroll
    for (int r = 0; r < 8; r++){ float e = __expf(x[r] - mx); x[r] = e; sum += e; }
    red[tid] = sum; __syncthreads();
    for (int off = 128; off > 0; off >>= 1){
        if (tid < off) red[tid] += red[tid + off];
        __syncthreads();
    }
    const float inv = 1.0f / red[0];

    #pragma unroll
    for (int r = 0; r < 8; r++){
        int t = tid + r * 256;
        pr[t] = mrow[t] ? __float2half(x[r] * inv) : __float2half(0.0f);
    }
}

// ---------------- LayerNorm ----------------
__global__ __launch_bounds__(256)
void layernorm_kernel(const float* __restrict__ h, const float* __restrict__ gamma,
                      const float* __restrict__ beta, float* __restrict__ out)
{
    const int row = blockIdx.x;
    const float* r = h + (size_t)row * HH;
    float* o = out + (size_t)row * HH;
    const int tid = threadIdx.x;

    float v0 = r[tid], v1 = r[tid + 256], v2 = r[tid + 512];
    float s = v0 + v1 + v2;
    float ss = v0*v0 + v1*v1 + v2*v2;

    __shared__ float rs[256], rss[256];
    rs[tid] = s; rss[tid] = ss; __syncthreads();
    for (int off = 128; off > 0; off >>= 1){
        if (tid < off){ rs[tid] += rs[tid + off]; rss[tid] += rss[tid + off]; }
        __syncthreads();
    }
    const float mu = rs[0] * (1.0f / HH);
    const float var = rss[0] * (1.0f / HH) - mu * mu;
    const float rstd = rsqrtf(var + 1e-12f);

    o[tid]       = (v0 - mu) * rstd * gamma[tid]       + beta[tid];
    o[tid + 256] = (v1 - mu) * rstd * gamma[tid + 256] + beta[tid + 256];
    o[tid + 512] = (v2 - mu) * rstd * gamma[tid + 512] + beta[tid + 512];
}

// ---------------- host ----------------
extern "C" void kernel_launch(void* const* d_in, const int* in_sizes, int n_in,
                              void* d_out, int out_size)
{
    const float* X     = (const float*)d_in[0];
    const int*   mask  = (const int*)  d_in[1];
    const float* Wq    = (const float*)d_in[2];
    const float* bq    = (const float*)d_in[3];
    const float* Wk    = (const float*)d_in[4];
    const float* bk    = (const float*)d_in[5];
    const float* Wv    = (const float*)d_in[6];
    const float* bv    = (const float*)d_in[7];
    const float* Wo    = (const float*)d_in[8];
    const float* bo    = (const float*)d_in[9];
    const float* gamma = (const float*)d_in[10];
    const float* beta  = (const float*)d_in[11];
    float* out = (float*)d_out;

    __half *xh, *wt, *qh, *kh, *vh, *vt, *ph, *ch;
    float *sc, *h;
    cudaGetSymbolAddress((void**)&xh, g_xh);
    cudaGetSymbolAddress((void**)&wt, g_wt);
    cudaGetSymbolAddress((void**)&qh, g_qh);
    cudaGetSymbolAddress((void**)&kh, g_kh);
    cudaGetSymbolAddress((void**)&vh, g_vh);
    cudaGetSymbolAddress((void**)&vt, g_vt);
    cudaGetSymbolAddress((void**)&ph, g_ph);
    cudaGetSymbolAddress((void**)&ch, g_ch);
    cudaGetSymbolAddress((void**)&sc, g_scores);
    cudaGetSymbolAddress((void**)&h,  g_h);

    const dim3 blk(256);
    const size_t WW = (size_t)HH * HH;

    // 0) conversions: X -> fp16, W -> W^T fp16
    {
        int n4 = MTOT * HH / 4;
        f32_to_f16<<<(n4 + 255)/256, blk>>>((const float4*)X, (__half2*)xh, n4);
        dim3 tg(HH/32, HH/32, 1);
        transpose_f32_to_f16<<<tg, blk>>>(Wq, wt + 0*WW, HH, HH);
        transpose_f32_to_f16<<<tg, blk>>>(Wk, wt + 1*WW, HH, HH);
        transpose_f32_to_f16<<<tg, blk>>>(Wv, wt + 2*WW, HH, HH);
        transpose_f32_to_f16<<<tg, blk>>>(Wo, wt + 3*WW, HH, HH);
    }

    // 1) QKV projections -> fp16
    {
        dim3 grid(HH/BNH, MTOT/BMH, 1);
        gemm_f16<<<grid, blk>>>(xh, wt + 0*WW, bq, nullptr, nullptr, qh, HH, HH, 0, 0, 0, 1.0f);
        gemm_f16<<<grid, blk>>>(xh, wt + 1*WW, bk, nullptr, nullptr, kh, HH, HH, 0, 0, 0, 1.0f);
        gemm_f16<<<grid, blk>>>(xh, wt + 2*WW, bv, nullptr, nullptr, vh, HH, HH, 0, 0, 0, 1.0f);
    }

    // 1b) v -> v^T per batch
    {
        dim3 tg(HH/32, SS/32, BB);
        transpose_f16<<<tg, blk>>>(vh, vt, SS, HH, (long long)SS*HH, (long long)HH*SS);
    }

    // 2) scores = q @ k^T / sqrt(H) -> fp32
    {
        dim3 grid(SS/BNH, SS/BMH, BB);
        gemm_f16<<<grid, blk>>>(qh, kh, nullptr, nullptr, sc, nullptr, HH, SS,
                                (long long)SS*HH, (long long)SS*HH, (long long)SS*SS,
                                1.0f/sqrtf((float)HH));
    }

    // 3) masked softmax -> fp16 probs
    {
        dim3 grid(SS, BB, 1);
        xsoftmax_f16<<<grid, blk>>>(sc, mask, ph);
    }

    // 4) ctx = probs @ v -> fp16
    {
        dim3 grid(HH/BNH, SS/BMH, BB);
        gemm_f16<<<grid, blk>>>(ph, vt, nullptr, nullptr, nullptr, ch, SS, HH,
                                (long long)SS*SS, (long long)HH*SS, (long long)SS*HH, 1.0f);
    }

    // 5) h = ctx @ Wo + bo + X -> fp32
    {
        dim3 grid(HH/BNH, MTOT/BMH, 1);
        gemm_f16<<<grid, blk>>>(ch, wt + 3*WW, bo, X, h, nullptr, HH, HH, 0, 0, 0, 1.0f);
    }

    // 6) LayerNorm -> out
    {
        dim3 grid(MTOT, 1, 1);
        layernorm_kernel<<<grid, blk>>>(h, gamma, beta, out);
    }
}

// round 6
// speedup vs baseline: 7.0181x; 1.3832x over previous
#include <cuda_runtime.h>
#include <cuda_fp16.h>
#include <math.h>
#include <stdint.h>

#define BB 8
#define SS 2048
#define HH 768
#define MTOT (BB*SS)   // 16384
#define NQKV 2304      // 3*HH

// ---------------- scratch (device globals) ----------------
__device__ __half g_xh[MTOT*HH];
__device__ __half g_wt[4*HH*HH];                 // W^T fp16: Wq,Wk,Wv rows 0..2303, Wo at +3*WW
__device__ float  g_bqkv[NQKV];
__device__ __half g_qkv[(size_t)MTOT*NQKV];      // q | k | v packed per row
__device__ __half g_vt[(size_t)BB*HH*SS];        // v^T per batch [H][S]
__device__ __half g_sc[(size_t)BB*SS*SS];        // fp16 scores -> probs (in-place)
__device__ __half g_ch[MTOT*HH];
__device__ float  g_h[MTOT*HH];

// ---------------- fp16 tensor-core GEMM (NT: C = alpha*A@B^T) ----------------
#define BMH 128
#define BNH 128
#define BKH 64
#define ROWB 144                    // 64 halfs = 128B -> pad to 144B
#define TILEB (BMH*ROWB)            // 18432
#define STAGEB (2*TILEB)            // 36864
#define GSMEM (2*STAGEB)            // 73728

__device__ __forceinline__ uint32_t smem_u32(const void* p){
    uint32_t a;
    asm("{ .reg .u64 t; cvta.to.shared.u64 t, %1; cvt.u32.u64 %0, t; }" : "=r"(a) : "l"(p));
    return a;
}
__device__ __forceinline__ void cp16(uint32_t smem, const void* gmem){
    asm volatile("cp.async.ca.shared.global [%0], [%1], 16;" :: "r"(smem), "l"(gmem));
}
__device__ __forceinline__ void ldsm4(uint32_t r[4], uint32_t addr){
    asm volatile("ldmatrix.sync.aligned.m8n8.x4.shared.b16 {%0,%1,%2,%3}, [%4];"
        : "=r"(r[0]), "=r"(r[1]), "=r"(r[2]), "=r"(r[3]) : "r"(addr));
}
__device__ __forceinline__ void mma_f16(float c[4],
        uint32_t a0, uint32_t a1, uint32_t a2, uint32_t a3,
        uint32_t b0, uint32_t b1){
    asm volatile(
        "mma.sync.aligned.m16n8k16.row.col.f32.f16.f16.f32 "
        "{%0,%1,%2,%3}, {%4,%5,%6,%7}, {%8,%9}, {%0,%1,%2,%3};"
        : "+f"(c[0]), "+f"(c[1]), "+f"(c[2]), "+f"(c[3])
        : "r"(a0), "r"(a1), "r"(a2), "r"(a3), "r"(b0), "r"(b1));
}

// A: [M,ldA] row-major fp16 (use K cols). B: [N,ldB] row-major fp16 (K-major).
__global__ __launch_bounds__(256, 2)
void gemm_f16(const __half* __restrict__ A, const __half* __restrict__ B,
              const float* __restrict__ bias, const float* __restrict__ res,
              float* __restrict__ Cf, __half* __restrict__ Ch,
              int K, int ldA, int ldB, int ldC,
              long long sA, long long sB, long long sC, float alpha)
{
    extern __shared__ __align__(128) char smem[];
    const uint32_t sbase = smem_u32(smem);

    A += (size_t)blockIdx.z * sA;
    B += (size_t)blockIdx.z * sB;
    if (Cf) Cf += (size_t)blockIdx.z * sC;
    if (Ch) Ch += (size_t)blockIdx.z * sC;

    const int tid  = threadIdx.x;
    const int lane = tid & 31;
    const int warp = tid >> 5;
    const int g    = lane >> 2;
    const int tg   = lane & 3;
    const int wm   = warp & 3;      // 4 warps on M (32 rows)
    const int wn   = warp >> 2;     // 2 warps on N (64 cols)
    const int m0   = blockIdx.y * BMH;
    const int n0   = blockIdx.x * BNH;
    const int NK   = K / BKH;

    float acc[2][8][4] = {};

    // fill: A tile 128 rows x 128B, B tile 128 rows x 128B; 8 cp16/thread
    auto fill = [&](int buf, int kt){
        const uint32_t sb = sbase + buf * STAGEB;
        const int k0 = kt * BKH;
        #pragma unroll
        for (int i = 0; i < 4; i++){
            int idx = tid + i * 256;
            int r = idx >> 3, c = idx & 7;
            cp16(sb + r * ROWB + c * 16, A + (size_t)(m0 + r) * ldA + k0 + c * 8);
        }
        #pragma unroll
        for (int i = 0; i < 4; i++){
            int idx = tid + i * 256;
            int r = idx >> 3, c = idx & 7;
            cp16(sb + TILEB + r * ROWB + c * 16, B + (size_t)(n0 + r) * ldB + k0 + c * 8);
        }
        asm volatile("cp.async.commit_group;");
    };

    // per-warp ldmatrix base addresses (lane-dependent)
    const uint32_t aOff = (uint32_t)((wm * 32 + (lane & 15)) * ROWB + ((lane >> 4) * 16));
    const uint32_t bOff = (uint32_t)((wn * 64 + (lane & 15)) * ROWB + ((lane >> 4) * 16));

    fill(0, 0);

    for (int kt = 0; kt < NK; kt++){
        asm volatile("cp.async.wait_group 0;");
        __syncthreads();
        if (kt + 1 < NK) fill((kt + 1) & 1, kt + 1);

        const uint32_t sb = sbase + (kt & 1) * STAGEB;
        const uint32_t aB = sb + aOff;
        const uint32_t bB = sb + TILEB + bOff;

        #pragma unroll
        for (int ks = 0; ks < 4; ks++){
            uint32_t af0[4], af1[4], bf[4][4];
            ldsm4(af0, aB + ks * 32);
            ldsm4(af1, aB + 16 * ROWB + ks * 32);
            #pragma unroll
            for (int pr = 0; pr < 4; pr++)
                ldsm4(bf[pr], bB + pr * 16 * ROWB + ks * 32);
            #pragma unroll
            for (int pr = 0; pr < 4; pr++){
                mma_f16(acc[0][2*pr  ], af0[0], af0[1], af0[2], af0[3], bf[pr][0], bf[pr][2]);
                mma_f16(acc[0][2*pr+1], af0[0], af0[1], af0[2], af0[3], bf[pr][1], bf[pr][3]);
                mma_f16(acc[1][2*pr  ], af1[0], af1[1], af1[2], af1[3], bf[pr][0], bf[pr][2]);
                mma_f16(acc[1][2*pr+1], af1[0], af1[1], af1[2], af1[3], bf[pr][1], bf[pr][3]);
            }
        }
    }

    // epilogue
    #pragma unroll
    for (int mt = 0; mt < 2; mt++){
        #pragma unroll
        for (int nt = 0; nt < 8; nt++){
            int row = m0 + wm * 32 + mt * 16 + g;
            int col = n0 + wn * 64 + nt * 8 + tg * 2;
            float2 v0 = make_float2(acc[mt][nt][0] * alpha, acc[mt][nt][1] * alpha);
            float2 v1 = make_float2(acc[mt][nt][2] * alpha, acc[mt][nt][3] * alpha);
            if (bias){
                float2 bb = *(const float2*)(bias + col);
                v0.x += bb.x; v0.y += bb.y; v1.x += bb.x; v1.y += bb.y;
            }
            if (res){
                float2 r0 = *(const float2*)(res + (size_t)row * ldC + col);
                float2 r1 = *(const float2*)(res + (size_t)(row + 8) * ldC + col);
                v0.x += r0.x; v0.y += r0.y; v1.x += r1.x; v1.y += r1.y;
            }
            if (Cf){
                *(float2*)(Cf + (size_t)row * ldC + col) = v0;
                *(float2*)(Cf + (size_t)(row + 8) * ldC + col) = v1;
            }
            if (Ch){
                *(__half2*)(Ch + (size_t)row * ldC + col) = __floats2half2_rn(v0.x, v0.y);
                *(__half2*)(Ch + (size_t)(row + 8) * ldC + col) = __floats2half2_rn(v1.x, v1.y);
            }
        }
    }
}

// ---------------- conversions ----------------
__global__ __launch_bounds__(256)
void f32_to_f16(const float4* __restrict__ in, __half2* __restrict__ out, int n4)
{
    int i = blockIdx.x * 256 + threadIdx.x;
    if (i >= n4) return;
    float4 v = in[i];
    out[2*i]   = __floats2half2_rn(v.x, v.y);
    out[2*i+1] = __floats2half2_rn(v.z, v.w);
}

// all four W [768][768] fp32 -> W^T fp16, z selects source
__global__ __launch_bounds__(256)
void transpose4_w(const float* __restrict__ W0, const float* __restrict__ W1,
                  const float* __restrict__ W2, const float* __restrict__ W3,
                  __half* __restrict__ outT)
{
    __shared__ float t[32][33];
    const float* in = (blockIdx.z == 0) ? W0 : (blockIdx.z == 1) ? W1
                    : (blockIdx.z == 2) ? W2 : W3;
    __half* o = outT + (size_t)blockIdx.z * HH * HH;
    const int c0 = blockIdx.x * 32, r0 = blockIdx.y * 32;
    const int tx = threadIdx.x & 31, ty = threadIdx.x >> 5;
    #pragma unroll
    for (int i = 0; i < 4; i++)
        t[ty + 8*i][tx] = in[(size_t)(r0 + ty + 8*i) * HH + c0 + tx];
    __syncthreads();
    #pragma unroll
    for (int i = 0; i < 4; i++)
        o[(size_t)(c0 + ty + 8*i) * HH + r0 + tx] = __float2half(t[tx][ty + 8*i]);
}

// fp16 [R][ldIn] (use C cols) -> fp16 [C][R], batched via z
__global__ __launch_bounds__(256)
void transpose_f16(const __half* __restrict__ in, __half* __restrict__ outT,
                   int R, int C, int ldIn, long long sIn, long long sOut)
{
    __shared__ __half t[32][34];
    in   += (size_t)blockIdx.z * sIn;
    outT += (size_t)blockIdx.z * sOut;
    const int c0 = blockIdx.x * 32, r0 = blockIdx.y * 32;
    const int tx = threadIdx.x & 31, ty = threadIdx.x >> 5;
    #pragma unroll
    for (int i = 0; i < 4; i++)
        t[ty + 8*i][tx] = in[(size_t)(r0 + ty + 8*i) * ldIn + c0 + tx];
    __syncthreads();
    #pragma unroll
    for (int i = 0; i < 4; i++)
        outT[(size_t)(c0 + ty + 8*i) * R + r0 + tx] = t[tx][ty + 8*i];
}

__global__ void concat_bias(const float* __restrict__ a, const float* __restrict__ b,
                            const float* __restrict__ c, float* __restrict__ out)
{
    int i = blockIdx.x * 256 + threadIdx.x;
    if (i < HH)            out[i] = a[i];
    else if (i < 2*HH)     out[i] = b[i - HH];
    else if (i < 3*HH)     out[i] = c[i - 2*HH];
}

// ---------------- XSoftmax fp16 in-place ----------------
__global__ __launch_bounds__(256)
void xsoftmax_f16(__half* __restrict__ sc, const int* __restrict__ mask)
{
    const int b = blockIdx.y;
    const int s = blockIdx.x;
    __half* row = sc + ((size_t)b * SS + s) * SS;
    const int* mrow = mask + (size_t)b * SS;
    const int tid = threadIdx.x;

    // 8 halfs per thread (one uint4), contiguous
    uint4 raw = ((const uint4*)row)[tid];
    __half2 hx[4];
    hx[0] = *(__half2*)&raw.x; hx[1] = *(__half2*)&raw.y;
    hx[2] = *(__half2*)&raw.z; hx[3] = *(__half2*)&raw.w;
    int4 ma = ((const int4*)mrow)[2*tid];
    int4 mb = ((const int4*)mrow)[2*tid + 1];
    int m[8] = {ma.x, ma.y, ma.z, ma.w, mb.x, mb.y, mb.z, mb.w};

    const float NEG = -3.402823466e38f;
    float x[8];
    float mx = NEG;
    #pragma unroll
    for (int j = 0; j < 4; j++){
        float2 f = __half22float2(hx[j]);
        x[2*j]   = m[2*j]   ? f.x : NEG;
        x[2*j+1] = m[2*j+1] ? f.y : NEG;
        mx = fmaxf(mx, fmaxf(x[2*j], x[2*j+1]));
    }

    __shared__ float red[256];
    red[tid] = mx; __syncthreads();
    for (int off = 128; off > 0; off >>= 1){
        if (tid < off) red[tid] = fmaxf(red[tid], red[tid + off]);
        __syncthreads();
    }
    mx = red[0]; __syncthreads();

    float sum = 0.f;
    #pragma unroll
    for (int j = 0; j < 8; j++){ float e = __expf(x[j] - mx); x[j] = e; sum += e; }
    red[tid] = sum; __syncthreads();
    for (int off = 128; off > 0; off >>= 1){
        if (tid < off) red[tid] += red[tid + off];
        __syncthreads();
    }
    const float inv = 1.0f / red[0];

    #pragma unroll
    for (int j = 0; j < 4; j++){
        float p0 = m[2*j]   ? x[2*j]   * inv : 0.0f;
        float p1 = m[2*j+1] ? x[2*j+1] * inv : 0.0f;
        hx[j] = __floats2half2_rn(p0, p1);
    }
    raw.x = *(uint32_t*)&hx[0]; raw.y = *(uint32_t*)&hx[1];
    raw.z = *(uint32_t*)&hx[2]; raw.w = *(uint32_t*)&hx[3];
    ((uint4*)row)[tid] = raw;
}

// ---------------- LayerNorm ----------------
__global__ __launch_bounds__(256)
void layernorm_kernel(const float* __restrict__ h, const float* __restrict__ gamma,
                      const float* __restrict__ beta, float* __restrict__ out)
{
    const int row = blockIdx.x;
    const float* r = h + (size_t)row * HH;
    float* o = out + (size_t)row * HH;
    const int tid = threadIdx.x;

    float v0 = r[tid], v1 = r[tid + 256], v2 = r[tid + 512];
    float s = v0 + v1 + v2;
    float ss = v0*v0 + v1*v1 + v2*v2;

    __shared__ float rs[256], rss[256];
    rs[tid] = s; rss[tid] = ss; __syncthreads();
    for (int off = 128; off > 0; off >>= 1){
        if (tid < off){ rs[tid] += rs[tid + off]; rss[tid] += rss[tid + off]; }
        __syncthreads();
    }
    const float mu = rs[0] * (1.0f / HH);
    const float var = rss[0] * (1.0f / HH) - mu * mu;
    const float rstd = rsqrtf(var + 1e-12f);

    o[tid]       = (v0 - mu) * rstd * gamma[tid]       + beta[tid];
    o[tid + 256] = (v1 - mu) * rstd * gamma[tid + 256] + beta[tid + 256];
    o[tid + 512] = (v2 - mu) * rstd * gamma[tid + 512] + beta[tid + 512];
}

// ---------------- host ----------------
extern "C" void kernel_launch(void* const* d_in, const int* in_sizes, int n_in,
                              void* d_out, int out_size)
{
    const float* X     = (const float*)d_in[0];
    const int*   mask  = (const int*)  d_in[1];
    const float* Wq    = (const float*)d_in[2];
    const float* bq    = (const float*)d_in[3];
    const float* Wk    = (const float*)d_in[4];
    const float* bk    = (const float*)d_in[5];
    const float* Wv    = (const float*)d_in[6];
    const float* bv    = (const float*)d_in[7];
    const float* Wo    = (const float*)d_in[8];
    const float* bo    = (const float*)d_in[9];
    const float* gamma = (const float*)d_in[10];
    const float* beta  = (const float*)d_in[11];
    float* out = (float*)d_out;

    __half *xh, *wt, *qkv, *vt, *sc, *ch;
    float *bqkv, *h;
    cudaGetSymbolAddress((void**)&xh,   g_xh);
    cudaGetSymbolAddress((void**)&wt,   g_wt);
    cudaGetSymbolAddress((void**)&bqkv, g_bqkv);
    cudaGetSymbolAddress((void**)&qkv,  g_qkv);
    cudaGetSymbolAddress((void**)&vt,   g_vt);
    cudaGetSymbolAddress((void**)&sc,   g_sc);
    cudaGetSymbolAddress((void**)&ch,   g_ch);
    cudaGetSymbolAddress((void**)&h,    g_h);

    static int smemSet = 0;
    if (!smemSet){
        cudaFuncSetAttribute(gemm_f16, cudaFuncAttributeMaxDynamicSharedMemorySize, GSMEM);
        smemSet = 1;
    }

    const dim3 blk(256);
    const size_t WW = (size_t)HH * HH;

    // 0) conversions
    {
        int n4 = MTOT * HH / 4;
        f32_to_f16<<<(n4 + 255)/256, blk>>>((const float4*)X, (__half2*)xh, n4);
        dim3 tg(HH/32, HH/32, 4);
        transpose4_w<<<tg, blk>>>(Wq, Wk, Wv, Wo, wt);
        concat_bias<<<(NQKV + 255)/256, blk>>>(bq, bk, bv, bqkv);
    }

    // 1) fused QKV: qkv[M,2304] = X @ [Wq|Wk|Wv] + b
    {
        dim3 grid(NQKV/BNH, MTOT/BMH, 1);
        gemm_f16<<<grid, blk, GSMEM>>>(xh, wt, bqkv, nullptr, nullptr, qkv,
                                       HH, HH, HH, NQKV, 0, 0, 0, 1.0f);
    }

    // 1b) v -> v^T per batch
    {
        dim3 tg(HH/32, SS/32, BB);
        transpose_f16<<<tg, blk>>>(qkv + 2*HH, vt, SS, HH, NQKV,
                                   (long long)SS*NQKV, (long long)HH*SS);
    }

    // 2) scores = q @ k^T / sqrt(H) -> fp16
    {
        dim3 grid(SS/BNH, SS/BMH, BB);
        gemm_f16<<<grid, blk, GSMEM>>>(qkv, qkv + HH, nullptr, nullptr, nullptr, sc,
                                       HH, NQKV, NQKV, SS,
                                       (long long)SS*NQKV, (long long)SS*NQKV,
                                       (long long)SS*SS, 1.0f/sqrtf((float)HH));
    }

    // 3) masked softmax in-place (fp16)
    {
        dim3 grid(SS, BB, 1);
        xsoftmax_f16<<<grid, blk>>>(sc, mask);
    }

    // 4) ctx = probs @ v -> fp16
    {
        dim3 grid(HH/BNH, SS/BMH, BB);
        gemm_f16<<<grid, blk, GSMEM>>>(sc, vt, nullptr, nullptr, nullptr, ch,
                                       SS, SS, SS, HH,
                                       (long long)SS*SS, (long long)HH*SS,
                                       (long long)SS*HH, 1.0f);
    }

    // 5) h = ctx @ Wo + bo + X -> fp32
    {
        dim3 grid(HH/BNH, MTOT/BMH, 1);
        gemm_f16<<<grid, blk, GSMEM>>>(ch, wt + 3*WW, bo, X, h, nullptr,
                                       HH, HH, HH, HH, 0, 0, 0, 1.0f);
    }

    // 6) LayerNorm -> out
    {
        dim3 grid(MTOT, 1, 1);
        layernorm_kernel<<<grid, blk>>>(h, gamma, beta, out);
    }
}